// round 4
// baseline (speedup 1.0000x reference)
#include <cuda_runtime.h>
#include <cstdint>

// ---------------------------------------------------------------------------
// StochLinear (base sm_103 feature set only — no tcgen05 in this build):
//   1) gen_bits_A/W: exact JAX threefry-2x32 (partitionable) -> int8 {0,1}
//      operands, K' = L*K = 16384, plus bit-count sums sA/sB.
//   2) mma.sync.m16n8k32 s8 GEMM (128x128 tiles, 4-stage cp.async pipeline),
//      fused epilogue:
//        out[b,n] = 0.5*S - 0.25*(sA[b]+sB[n]) + 2048 + bias[n]   (exact fp32)
// ---------------------------------------------------------------------------

#define B_DIM 4096
#define K_DIM 2048
#define N_DIM 2048
#define KTOT  (K_DIM * 8)          // 16384
#define BM 128
#define BN 128
#define BK 64
#define NSTEP (KTOT / BK)          // 256
#define PITCH 80                   // 64B row + 16B pad: conflict-free LDS
#define STAGE_BYTES (2 * BM * PITCH)   // A tile + B tile per stage = 20480
#define NSTAGES 4
#define SMEM_BYTES (NSTAGES * STAGE_BYTES)  // 81920

__device__ uint8_t g_A[(size_t)B_DIM * KTOT];   // 64 MB
__device__ uint8_t g_W[(size_t)N_DIM * KTOT];   // 32 MB
__device__ int g_sA[B_DIM];
__device__ int g_sB[N_DIM];

// ---------------- Threefry-2x32 (20 rounds) --------------------------------
__host__ __device__ __forceinline__ void tf2x32(uint32_t k0, uint32_t k1,
                                                uint32_t x0, uint32_t x1,
                                                uint32_t &o0, uint32_t &o1)
{
    uint32_t ks2 = k0 ^ k1 ^ 0x1BD11BDAu;
    x0 += k0; x1 += k1;
#define TFR(r) { x0 += x1; x1 = (x1 << (r)) | (x1 >> (32 - (r))); x1 ^= x0; }
    TFR(13) TFR(15) TFR(26) TFR(6)
    x0 += k1;  x1 += ks2 + 1u;
    TFR(17) TFR(29) TFR(16) TFR(24)
    x0 += ks2; x1 += k0 + 2u;
    TFR(13) TFR(15) TFR(26) TFR(6)
    x0 += k0;  x1 += k1 + 3u;
    TFR(17) TFR(29) TFR(16) TFR(24)
    x0 += k1;  x1 += ks2 + 4u;
    TFR(13) TFR(15) TFR(26) TFR(6)
    x0 += ks2; x1 += k0 + 5u;
#undef TFR
    o0 = x0; o1 = x1;
}

__device__ __forceinline__ float unit_f32(uint32_t bits)
{
    return __uint_as_float((bits >> 9) | 0x3F800000u) - 1.0f;
}

// ---------------- bitgen A: (L,B,K), ctr = (l<<23)|(b<<11)|k ---------------
__global__ void __launch_bounds__(256) gen_bits_A(const float* __restrict__ x,
                                                  uint32_t k0, uint32_t k1)
{
    int b  = blockIdx.x;
    int kk = threadIdx.x * 8;
    const float* xr = x + (size_t)b * K_DIM + kk;
    float p[8];
#pragma unroll
    for (int j = 0; j < 8; ++j)
        p[j] = fminf(fmaxf((xr[j] + 1.0f) * 0.5f, 0.0f), 1.0f);
    uint32_t base = ((uint32_t)b << 11) | (uint32_t)kk;
    int cnt = 0;
#pragma unroll
    for (int l = 0; l < 8; ++l) {
        uint32_t w0 = 0, w1 = 0;
#pragma unroll
        for (int j = 0; j < 8; ++j) {
            uint32_t o0, o1;
            tf2x32(k0, k1, 0u, ((uint32_t)l << 23) | (base + j), o0, o1);
            uint32_t bit = (unit_f32(o0 ^ o1) < p[j]) ? 1u : 0u;
            cnt += (int)bit;
            if (j < 4) w0 |= bit << (8 * j);
            else       w1 |= bit << (8 * (j - 4));
        }
        *reinterpret_cast<uint2*>(&g_A[(size_t)b * KTOT + l * K_DIM + kk]) =
            make_uint2(w0, w1);
    }
#pragma unroll
    for (int o = 16; o > 0; o >>= 1) cnt += __shfl_down_sync(0xffffffffu, cnt, o);
    if ((threadIdx.x & 31) == 0) atomicAdd(&g_sA[b], cnt);
}

// ---------------- bitgen W: (L,K,N), ctr = (l<<22)|(k<<11)|n ---------------
__global__ void __launch_bounds__(256) gen_bits_W(const float* __restrict__ w,
                                                  uint32_t k0, uint32_t k1)
{
    int nn = blockIdx.x;
    int kk = threadIdx.x * 8;
    const float* wr = w + (size_t)nn * K_DIM + kk;
    float p[8];
#pragma unroll
    for (int j = 0; j < 8; ++j)
        p[j] = fminf(fmaxf((wr[j] + 1.0f) * 0.5f, 0.0f), 1.0f);
    int cnt = 0;
#pragma unroll
    for (int l = 0; l < 8; ++l) {
        uint32_t w0 = 0, w1 = 0;
#pragma unroll
        for (int j = 0; j < 8; ++j) {
            uint32_t c = ((uint32_t)l << 22) | ((uint32_t)(kk + j) << 11) | (uint32_t)nn;
            uint32_t o0, o1;
            tf2x32(k0, k1, 0u, c, o0, o1);
            uint32_t bit = (unit_f32(o0 ^ o1) < p[j]) ? 1u : 0u;
            cnt += (int)bit;
            if (j < 4) w0 |= bit << (8 * j);
            else       w1 |= bit << (8 * (j - 4));
        }
        *reinterpret_cast<uint2*>(&g_W[(size_t)nn * KTOT + l * K_DIM + kk]) =
            make_uint2(w0, w1);
    }
#pragma unroll
    for (int o = 16; o > 0; o >>= 1) cnt += __shfl_down_sync(0xffffffffu, cnt, o);
    if ((threadIdx.x & 31) == 0) atomicAdd(&g_sB[nn], cnt);
}

__global__ void zero_counts()
{
    int i = blockIdx.x * blockDim.x + threadIdx.x;
    if (i < B_DIM) g_sA[i] = 0;
    if (i < N_DIM) g_sB[i] = 0;
}

// ---------------- IMMA GEMM helpers ---------------------------------------
__device__ __forceinline__ uint32_t smem_u32(const void* p)
{
    uint32_t a;
    asm("{ .reg .u64 t; cvta.to.shared.u64 t, %1; cvt.u32.u64 %0, t; }" : "=r"(a) : "l"(p));
    return a;
}
__device__ __forceinline__ void cp16(uint32_t dst, const void* src)
{
    asm volatile("cp.async.cg.shared.global [%0], [%1], 16;" :: "r"(dst), "l"(src));
}
__device__ __forceinline__ uint32_t lds32(uint32_t addr)
{
    uint32_t v;
    asm volatile("ld.shared.b32 %0, [%1];" : "=r"(v) : "r"(addr));
    return v;
}
__device__ __forceinline__ void mma_s8(int* c, const uint32_t* a, const uint32_t* b)
{
    asm volatile(
        "mma.sync.aligned.m16n8k32.row.col.s32.s8.s8.s32 "
        "{%0,%1,%2,%3}, {%4,%5,%6,%7}, {%8,%9}, {%0,%1,%2,%3};"
        : "+r"(c[0]), "+r"(c[1]), "+r"(c[2]), "+r"(c[3])
        : "r"(a[0]), "r"(a[1]), "r"(a[2]), "r"(a[3]), "r"(b[0]), "r"(b[1]));
}
#define CP_COMMIT() asm volatile("cp.async.commit_group;" ::: "memory")
#define CP_WAIT2()  asm volatile("cp.async.wait_group 2;" ::: "memory")

// ---------------- GEMM: 128x128 tile, 8 warps (2x4), warp tile 64x32 ------
__global__ void __launch_bounds__(256, 2) gemm_imma(const float* __restrict__ bias,
                                                    float* __restrict__ out)
{
    extern __shared__ char sm[];
    uint32_t sb = smem_u32(sm);

    int tid  = threadIdx.x;
    int lane = tid & 31;
    int wid  = tid >> 5;
    int wm   = wid >> 2;       // 0..1  (64 rows each)
    int wn   = wid & 3;        // 0..3  (32 cols each)
    int g    = lane >> 2;      // 0..7
    int tig  = lane & 3;       // 0..3
    int row0 = blockIdx.y * BM;
    int col0 = blockIdx.x * BN;

    int acc[4][4][4];
#pragma unroll
    for (int i = 0; i < 4; ++i)
#pragma unroll
        for (int j = 0; j < 4; ++j)
#pragma unroll
            for (int q = 0; q < 4; ++q) acc[i][j][q] = 0;

    // ---- stage loader: A tile [128 x 64B], B tile [128 x 64B], pitch 80 ----
    auto load_stage = [&](int kt, int s) {
        uint32_t dstA = sb + s * STAGE_BYTES;
        uint32_t dstB = dstA + BM * PITCH;
        const uint8_t* srcA = g_A + (size_t)row0 * KTOT + (size_t)kt * BK;
        const uint8_t* srcB = g_W + (size_t)col0 * KTOT + (size_t)kt * BK;
#pragma unroll
        for (int q = 0; q < 2; ++q) {
            int task = tid + q * 256;          // 512 tasks: row = task>>2, chunk = task&3
            int r = task >> 2, ch = task & 3;
            cp16(dstA + r * PITCH + ch * 16, srcA + (size_t)r * KTOT + ch * 16);
        }
#pragma unroll
        for (int q = 0; q < 2; ++q) {
            int task = tid + q * 256;
            int r = task >> 2, ch = task & 3;
            cp16(dstB + r * PITCH + ch * 16, srcB + (size_t)r * KTOT + ch * 16);
        }
    };

    load_stage(0, 0); CP_COMMIT();
    load_stage(1, 1); CP_COMMIT();
    load_stage(2, 2); CP_COMMIT();

    for (int kt = 0; kt < NSTEP; ++kt) {
        CP_WAIT2();
        __syncthreads();

        uint32_t aB = sb + (kt & 3) * STAGE_BYTES;
        uint32_t bB = aB + BM * PITCH;
#pragma unroll
        for (int ks = 0; ks < 2; ++ks) {
            uint32_t a[4][4], bf[4][2];
            uint32_t cb = (uint32_t)(ks * 32 + tig * 4);
#pragma unroll
            for (int mt = 0; mt < 4; ++mt) {
                uint32_t r = (uint32_t)(wm * 64 + mt * 16 + g);
                a[mt][0] = lds32(aB + r * PITCH + cb);
                a[mt][1] = lds32(aB + (r + 8) * PITCH + cb);
                a[mt][2] = lds32(aB + r * PITCH + cb + 16);
                a[mt][3] = lds32(aB + (r + 8) * PITCH + cb + 16);
            }
#pragma unroll
            for (int nt = 0; nt < 4; ++nt) {
                uint32_t n = (uint32_t)(wn * 32 + nt * 8 + g);
                bf[nt][0] = lds32(bB + n * PITCH + cb);
                bf[nt][1] = lds32(bB + n * PITCH + cb + 16);
            }
#pragma unroll
            for (int mt = 0; mt < 4; ++mt)
#pragma unroll
                for (int nt = 0; nt < 4; ++nt)
                    mma_s8(acc[mt][nt], a[mt], bf[nt]);
        }
        __syncthreads();
        if (kt + 3 < NSTEP) load_stage(kt + 3, (kt + 3) & 3);
        CP_COMMIT();   // always commit so wait_group counting stays aligned
    }

    // ---- epilogue: out = 0.5*S - 0.25*(sA+sB) + 2048 + bias (exact) -------
#pragma unroll
    for (int mt = 0; mt < 4; ++mt) {
#pragma unroll
        for (int half = 0; half < 2; ++half) {
            int row = row0 + wm * 64 + mt * 16 + g + half * 8;
            float sa = (float)__ldg(&g_sA[row]);
            float* orow = out + (size_t)row * N_DIM;
#pragma unroll
            for (int nt = 0; nt < 4; ++nt) {
                int col = col0 + wn * 32 + nt * 8 + tig * 2;
                float s0 = (float)acc[mt][nt][half * 2 + 0];
                float s1 = (float)acc[mt][nt][half * 2 + 1];
                float2 ov;
                ov.x = 0.5f * s0 - 0.25f * (sa + (float)__ldg(&g_sB[col]))
                     + 2048.0f + __ldg(&bias[col]);
                ov.y = 0.5f * s1 - 0.25f * (sa + (float)__ldg(&g_sB[col + 1]))
                     + 2048.0f + __ldg(&bias[col + 1]);
                *reinterpret_cast<float2*>(&orow[col]) = ov;
            }
        }
    }
}

// ---------------------------------------------------------------------------
extern "C" void kernel_launch(void* const* d_in, const int* in_sizes, int n_in,
                              void* d_out, int out_size)
{
    const float* x    = (const float*)d_in[0];
    const float* w    = (const float*)d_in[1];
    const float* bias = (const float*)d_in[2];
    float* out        = (float*)d_out;

    // jax.random.split(jax.random.key(42)), partitionable (foldlike)
    uint32_t kA0, kA1, kB0, kB1;
    tf2x32(0u, 42u, 0u, 0u, kA0, kA1);
    tf2x32(0u, 42u, 0u, 1u, kB0, kB1);

    static bool attr_set = false;
    if (!attr_set) {
        cudaFuncSetAttribute(gemm_imma,
                             cudaFuncAttributeMaxDynamicSharedMemorySize,
                             SMEM_BYTES);
        attr_set = true;
    }

    zero_counts<<<16, 256>>>();
    gen_bits_A<<<B_DIM, 256>>>(x, kA0, kA1);
    gen_bits_W<<<N_DIM, 256>>>(w, kB0, kB1);
    gemm_imma<<<dim3(N_DIM / BN, B_DIM / BM), 256, SMEM_BYTES>>>(bias, out);
}

// round 5
// speedup vs baseline: 1.8334x; 1.8334x over previous
#include <cuda_runtime.h>
#include <cstdint>

// ---------------------------------------------------------------------------
// StochLinear: exact JAX threefry bits -> bit-packed popcount GEMM v2.
//   out[b,n] = 0.5*S - 0.25*(sA[b]+sB[n]) + 2048 + bias[n]      (exact fp32)
// v2 GEMM: 128x128 tiles, 2-stage cp.async pipeline, XOR-swizzled row-major
// smem, 8x8 register tile with stride-16 mapping, 2 CTAs/SM.
// ---------------------------------------------------------------------------

#define B_DIM 4096
#define K_DIM 2048
#define N_DIM 2048
#define ROW_WORDS 512              // 8 l-slices * 64 words
#define CW   32                    // words per k-chunk
#define NCH  (ROW_WORDS / CW)      // 16
#define STG  16384                 // bytes per matrix tile per stage (128*128B)
#define SMEM_BYTES (2 * 2 * STG)   // 65536

__device__ uint32_t g_Apack[(size_t)B_DIM * ROW_WORDS]; // 8 MB
__device__ uint32_t g_Wpack[(size_t)N_DIM * ROW_WORDS]; // 4 MB
__device__ int g_sA[B_DIM];
__device__ int g_sB[N_DIM];

// ---------------- Threefry-2x32 (20 rounds) --------------------------------
__host__ __device__ __forceinline__ void tf2x32(uint32_t k0, uint32_t k1,
                                                uint32_t x0, uint32_t x1,
                                                uint32_t &o0, uint32_t &o1)
{
    uint32_t ks2 = k0 ^ k1 ^ 0x1BD11BDAu;
    x0 += k0; x1 += k1;
#define TFR(r) { x0 += x1; x1 = (x1 << (r)) | (x1 >> (32 - (r))); x1 ^= x0; }
    TFR(13) TFR(15) TFR(26) TFR(6)
    x0 += k1;  x1 += ks2 + 1u;
    TFR(17) TFR(29) TFR(16) TFR(24)
    x0 += ks2; x1 += k0 + 2u;
    TFR(13) TFR(15) TFR(26) TFR(6)
    x0 += k0;  x1 += k1 + 3u;
    TFR(17) TFR(29) TFR(16) TFR(24)
    x0 += k1;  x1 += ks2 + 4u;
    TFR(13) TFR(15) TFR(26) TFR(6)
    x0 += ks2; x1 += k0 + 5u;
#undef TFR
    o0 = x0; o1 = x1;
}

__device__ __forceinline__ float unit_f32(uint32_t bits)
{
    return __uint_as_float((bits >> 9) | 0x3F800000u) - 1.0f;
}

// ---------------- bitgen A: (L,B,K), ctr = (l<<23)|(b<<11)|k  (R2, proven) --
__global__ void __launch_bounds__(256) gen_bits_A(const float* __restrict__ x,
                                                  uint32_t k0, uint32_t k1)
{
    int t  = threadIdx.x;
    int b  = blockIdx.x * 4 + (t >> 6);
    int kw = t & 63;
    const float* xr = x + (size_t)b * K_DIM + (size_t)kw * 32;

    uint32_t words[8] = {0,0,0,0,0,0,0,0};
    for (int j = 0; j < 32; ++j) {
        float v = xr[j];
        float p = fminf(fmaxf((v + 1.0f) * 0.5f, 0.0f), 1.0f);
        uint32_t base = ((uint32_t)b << 11) | (uint32_t)(kw * 32 + j);
#pragma unroll
        for (int l = 0; l < 8; ++l) {
            uint32_t o0, o1;
            tf2x32(k0, k1, 0u, ((uint32_t)l << 23) | base, o0, o1);
            if (unit_f32(o0 ^ o1) < p) words[l] |= (1u << j);
        }
    }
    int cnt = 0;
#pragma unroll
    for (int l = 0; l < 8; ++l) {
        g_Apack[(size_t)b * ROW_WORDS + l * 64 + kw] = words[l];
        cnt += __popc(words[l]);
    }
#pragma unroll
    for (int o = 16; o > 0; o >>= 1) cnt += __shfl_down_sync(0xffffffffu, cnt, o);
    if ((t & 31) == 0) atomicAdd(&g_sA[b], cnt);
}

// ---------------- bitgen W: (L,K,N), ctr = (l<<22)|(k<<11)|n  (R2, proven) --
__global__ void __launch_bounds__(256) gen_bits_W(const float* __restrict__ w,
                                                  uint32_t k0, uint32_t k1)
{
    int t  = threadIdx.x;
    int nn = blockIdx.x * 4 + (t >> 6);
    int kw = t & 63;
    const float* wr = w + (size_t)nn * K_DIM + (size_t)kw * 32;

    uint32_t words[8] = {0,0,0,0,0,0,0,0};
    for (int j = 0; j < 32; ++j) {
        float v = wr[j];
        float p = fminf(fmaxf((v + 1.0f) * 0.5f, 0.0f), 1.0f);
        uint32_t kk = (uint32_t)(kw * 32 + j);
        uint32_t base = (kk << 11) | (uint32_t)nn;
#pragma unroll
        for (int l = 0; l < 8; ++l) {
            uint32_t o0, o1;
            tf2x32(k0, k1, 0u, ((uint32_t)l << 22) | base, o0, o1);
            if (unit_f32(o0 ^ o1) < p) words[l] |= (1u << j);
        }
    }
    int cnt = 0;
#pragma unroll
    for (int l = 0; l < 8; ++l) {
        g_Wpack[(size_t)nn * ROW_WORDS + l * 64 + kw] = words[l];
        cnt += __popc(words[l]);
    }
#pragma unroll
    for (int o = 16; o > 0; o >>= 1) cnt += __shfl_down_sync(0xffffffffu, cnt, o);
    if ((t & 31) == 0) atomicAdd(&g_sB[nn], cnt);
}

__global__ void zero_counts()
{
    int i = blockIdx.x * blockDim.x + threadIdx.x;
    if (i < B_DIM) g_sA[i] = 0;
    if (i < N_DIM) g_sB[i] = 0;
}

// ---------------- popc GEMM v2 ---------------------------------------------
__device__ __forceinline__ uint32_t smem_u32(const void* p)
{
    uint32_t a;
    asm("{ .reg .u64 t; cvta.to.shared.u64 t, %1; cvt.u32.u64 %0, t; }" : "=r"(a) : "l"(p));
    return a;
}
__device__ __forceinline__ void cp16(uint32_t dst, const void* src)
{
    asm volatile("cp.async.cg.shared.global [%0], [%1], 16;" :: "r"(dst), "l"(src));
}
#define CP_COMMIT() asm volatile("cp.async.commit_group;" ::: "memory")
#define CP_WAIT1()  asm volatile("cp.async.wait_group 1;" ::: "memory")
#define CP_WAIT0()  asm volatile("cp.async.wait_group 0;" ::: "memory")

__global__ void __launch_bounds__(256, 2) popc_gemm2(const float* __restrict__ bias,
                                                     float* __restrict__ out)
{
    extern __shared__ char smraw[];
    uint32_t sb = smem_u32(smraw);

    int tid = threadIdx.x;
    int tx  = tid & 15;
    int ty  = tid >> 4;
    int row0 = blockIdx.y * 128;
    int col0 = blockIdx.x * 128;

    // stage loader: A tile rows [row0,+128), B tile rows [col0,+128),
    // 32 words (128B) per row, chunk ch (16B) stored at (ch ^ (r&7)).
    auto load_stage = [&](int kt, int s) {
        uint32_t dst0 = sb + (uint32_t)s * (2 * STG);
#pragma unroll
        for (int q = 0; q < 8; ++q) {
            int task = tid + q * 256;          // 0..2047
            int mat  = task >> 10;             // 0 = A, 1 = B
            int rem  = task & 1023;
            int r    = rem >> 3;
            int ch   = rem & 7;
            uint32_t dst = dst0 + (uint32_t)mat * STG + (uint32_t)r * 128
                         + (uint32_t)((ch ^ (r & 7)) << 4);
            const uint32_t* src = mat
                ? &g_Wpack[(size_t)(col0 + r) * ROW_WORDS + kt * CW + ch * 4]
                : &g_Apack[(size_t)(row0 + r) * ROW_WORDS + kt * CW + ch * 4];
            cp16(dst, src);
        }
    };

    int acc[8][8];
#pragma unroll
    for (int i = 0; i < 8; ++i)
#pragma unroll
        for (int j = 0; j < 8; ++j) acc[i][j] = 0;

    load_stage(0, 0); CP_COMMIT();
    load_stage(1, 1); CP_COMMIT();

    uint32_t sA7 = (uint32_t)(ty & 7);
    uint32_t sB7 = (uint32_t)(tx & 7);

    for (int kt = 0; kt < NCH; ++kt) {
        if (kt < NCH - 2) { CP_WAIT1(); } else { CP_WAIT0(); }
        __syncthreads();

        const uint32_t* A = (const uint32_t*)(smraw + (size_t)(kt & 1) * (2 * STG));
        const uint32_t* Bm = A + STG / 4;

#pragma unroll 4
        for (int w = 0; w < CW; ++w) {
            uint32_t wordA = ((((uint32_t)w >> 2) ^ sA7) << 2) | ((uint32_t)w & 3);
            uint32_t wordB = ((((uint32_t)w >> 2) ^ sB7) << 2) | ((uint32_t)w & 3);
            uint32_t a[8], b[8];
#pragma unroll
            for (int i = 0; i < 8; ++i)
                a[i] = A[(uint32_t)(ty + 16 * i) * 32 + wordA];
#pragma unroll
            for (int j = 0; j < 8; ++j)
                b[j] = Bm[(uint32_t)(tx + 16 * j) * 32 + wordB];
#pragma unroll
            for (int i = 0; i < 8; ++i)
#pragma unroll
                for (int j = 0; j < 8; ++j)
                    acc[i][j] += __popc(a[i] & b[j]);
        }
        __syncthreads();
        if (kt + 2 < NCH) { load_stage(kt + 2, kt & 1); CP_COMMIT(); }
    }

    // epilogue: out = 0.5*S - 0.25*(sA+sB) + 2048 + bias   (exact in fp32)
#pragma unroll
    for (int i = 0; i < 8; ++i) {
        int row = row0 + ty + 16 * i;
        float sa = (float)__ldg(&g_sA[row]);
        float* orow = out + (size_t)row * N_DIM;
#pragma unroll
        for (int j = 0; j < 8; ++j) {
            int col = col0 + tx + 16 * j;
            float s = (float)acc[i][j];
            orow[col] = 0.5f * s - 0.25f * (sa + (float)__ldg(&g_sB[col]))
                      + 2048.0f + __ldg(&bias[col]);
        }
    }
}

// ---------------------------------------------------------------------------
extern "C" void kernel_launch(void* const* d_in, const int* in_sizes, int n_in,
                              void* d_out, int out_size)
{
    const float* x    = (const float*)d_in[0];
    const float* w    = (const float*)d_in[1];
    const float* bias = (const float*)d_in[2];
    float* out        = (float*)d_out;

    // jax.random.split(jax.random.key(42)), partitionable (foldlike)
    uint32_t kA0, kA1, kB0, kB1;
    tf2x32(0u, 42u, 0u, 0u, kA0, kA1);
    tf2x32(0u, 42u, 0u, 1u, kB0, kB1);

    cudaFuncSetAttribute(popc_gemm2,
                         cudaFuncAttributeMaxDynamicSharedMemorySize, SMEM_BYTES);

    zero_counts<<<16, 256>>>();
    gen_bits_A<<<B_DIM / 4, 256>>>(x, kA0, kA1);
    gen_bits_W<<<N_DIM / 4, 256>>>(w, kB0, kB1);
    popc_gemm2<<<dim3(N_DIM / 128, B_DIM / 128), 256, SMEM_BYTES>>>(bias, out);
}

// round 6
// speedup vs baseline: 2.4666x; 1.3454x over previous
#include <cuda_runtime.h>
#include <cstdint>

// ---------------------------------------------------------------------------
// StochLinear: exact JAX threefry bits -> bit-packed popcount GEMM v3.
//   out[b,n] = 0.5*S - 0.25*(sA[b]+sB[n]) + 2048 + bias[n]      (exact fp32)
// v3 GEMM: POPC is quarter-rate (XU pipe, rt8/SMSP) and was the binding pipe.
// CSA 7->3 compression (LOP3 XOR3/MAJ3 on the half-rate alu pipe) halves the
// POPC count: 4 POPC per 8 AND-words. LDS.128 operand loads, 2-stage cp.async.
// ---------------------------------------------------------------------------

#define B_DIM 4096
#define K_DIM 2048
#define N_DIM 2048
#define ROW_WORDS 512              // 8 l-slices * 64 words
#define CW   32                    // words per k-chunk
#define NCH  (ROW_WORDS / CW)      // 16
#define STG  16384                 // bytes per matrix tile per stage (128*128B)
#define SMEM_BYTES (2 * 2 * STG)   // 65536

__device__ uint32_t g_Apack[(size_t)B_DIM * ROW_WORDS]; // 8 MB
__device__ uint32_t g_Wpack[(size_t)N_DIM * ROW_WORDS]; // 4 MB
__device__ int g_sA[B_DIM];
__device__ int g_sB[N_DIM];

// ---------------- Threefry-2x32 (20 rounds) --------------------------------
__host__ __device__ __forceinline__ void tf2x32(uint32_t k0, uint32_t k1,
                                                uint32_t x0, uint32_t x1,
                                                uint32_t &o0, uint32_t &o1)
{
    uint32_t ks2 = k0 ^ k1 ^ 0x1BD11BDAu;
    x0 += k0; x1 += k1;
#define TFR(r) { x0 += x1; x1 = (x1 << (r)) | (x1 >> (32 - (r))); x1 ^= x0; }
    TFR(13) TFR(15) TFR(26) TFR(6)
    x0 += k1;  x1 += ks2 + 1u;
    TFR(17) TFR(29) TFR(16) TFR(24)
    x0 += ks2; x1 += k0 + 2u;
    TFR(13) TFR(15) TFR(26) TFR(6)
    x0 += k0;  x1 += k1 + 3u;
    TFR(17) TFR(29) TFR(16) TFR(24)
    x0 += k1;  x1 += ks2 + 4u;
    TFR(13) TFR(15) TFR(26) TFR(6)
    x0 += ks2; x1 += k0 + 5u;
#undef TFR
    o0 = x0; o1 = x1;
}

__device__ __forceinline__ float unit_f32(uint32_t bits)
{
    return __uint_as_float((bits >> 9) | 0x3F800000u) - 1.0f;
}

// ---------------- bitgen A: (L,B,K), ctr = (l<<23)|(b<<11)|k  (proven) ------
__global__ void __launch_bounds__(256) gen_bits_A(const float* __restrict__ x,
                                                  uint32_t k0, uint32_t k1)
{
    int t  = threadIdx.x;
    int b  = blockIdx.x * 4 + (t >> 6);
    int kw = t & 63;
    const float* xr = x + (size_t)b * K_DIM + (size_t)kw * 32;

    uint32_t words[8] = {0,0,0,0,0,0,0,0};
    for (int j = 0; j < 32; ++j) {
        float v = xr[j];
        float p = fminf(fmaxf((v + 1.0f) * 0.5f, 0.0f), 1.0f);
        uint32_t base = ((uint32_t)b << 11) | (uint32_t)(kw * 32 + j);
#pragma unroll
        for (int l = 0; l < 8; ++l) {
            uint32_t o0, o1;
            tf2x32(k0, k1, 0u, ((uint32_t)l << 23) | base, o0, o1);
            if (unit_f32(o0 ^ o1) < p) words[l] |= (1u << j);
        }
    }
    int cnt = 0;
#pragma unroll
    for (int l = 0; l < 8; ++l) {
        g_Apack[(size_t)b * ROW_WORDS + l * 64 + kw] = words[l];
        cnt += __popc(words[l]);
    }
#pragma unroll
    for (int o = 16; o > 0; o >>= 1) cnt += __shfl_down_sync(0xffffffffu, cnt, o);
    if ((t & 31) == 0) atomicAdd(&g_sA[b], cnt);
}

// ---------------- bitgen W: (L,K,N), ctr = (l<<22)|(k<<11)|n  (proven) ------
__global__ void __launch_bounds__(256) gen_bits_W(const float* __restrict__ w,
                                                  uint32_t k0, uint32_t k1)
{
    int t  = threadIdx.x;
    int nn = blockIdx.x * 4 + (t >> 6);
    int kw = t & 63;
    const float* wr = w + (size_t)nn * K_DIM + (size_t)kw * 32;

    uint32_t words[8] = {0,0,0,0,0,0,0,0};
    for (int j = 0; j < 32; ++j) {
        float v = wr[j];
        float p = fminf(fmaxf((v + 1.0f) * 0.5f, 0.0f), 1.0f);
        uint32_t kk = (uint32_t)(kw * 32 + j);
        uint32_t base = (kk << 11) | (uint32_t)nn;
#pragma unroll
        for (int l = 0; l < 8; ++l) {
            uint32_t o0, o1;
            tf2x32(k0, k1, 0u, ((uint32_t)l << 22) | base, o0, o1);
            if (unit_f32(o0 ^ o1) < p) words[l] |= (1u << j);
        }
    }
    int cnt = 0;
#pragma unroll
    for (int l = 0; l < 8; ++l) {
        g_Wpack[(size_t)nn * ROW_WORDS + l * 64 + kw] = words[l];
        cnt += __popc(words[l]);
    }
#pragma unroll
    for (int o = 16; o > 0; o >>= 1) cnt += __shfl_down_sync(0xffffffffu, cnt, o);
    if ((t & 31) == 0) atomicAdd(&g_sB[nn], cnt);
}

__global__ void zero_counts()
{
    int i = blockIdx.x * blockDim.x + threadIdx.x;
    if (i < B_DIM) g_sA[i] = 0;
    if (i < N_DIM) g_sB[i] = 0;
}

// ---------------- popc GEMM v3 ---------------------------------------------
__device__ __forceinline__ uint32_t smem_u32(const void* p)
{
    uint32_t a;
    asm("{ .reg .u64 t; cvta.to.shared.u64 t, %1; cvt.u32.u64 %0, t; }" : "=r"(a) : "l"(p));
    return a;
}
__device__ __forceinline__ void cp16(uint32_t dst, const void* src)
{
    asm volatile("cp.async.cg.shared.global [%0], [%1], 16;" :: "r"(dst), "l"(src));
}
#define CP_COMMIT() asm volatile("cp.async.commit_group;" ::: "memory")
#define CP_WAIT1()  asm volatile("cp.async.wait_group 1;" ::: "memory")
#define CP_WAIT0()  asm volatile("cp.async.wait_group 0;" ::: "memory")

__device__ __forceinline__ uint32_t xor3(uint32_t a, uint32_t b, uint32_t c)
{
    uint32_t r;
    asm("lop3.b32 %0, %1, %2, %3, 0x96;" : "=r"(r) : "r"(a), "r"(b), "r"(c));
    return r;
}
__device__ __forceinline__ uint32_t maj3(uint32_t a, uint32_t b, uint32_t c)
{
    uint32_t r;
    asm("lop3.b32 %0, %1, %2, %3, 0xE8;" : "=r"(r) : "r"(a), "r"(b), "r"(c));
    return r;
}

// CSA 7->3 + 1 naive over 8 AND-words: 4 POPC instead of 8.
__device__ __forceinline__ void csa8(int &acc,
                                     const uint4 &a0, const uint4 &a1,
                                     const uint4 &b0, const uint4 &b1)
{
    uint32_t x0 = a0.x & b0.x, x1 = a0.y & b0.y;
    uint32_t x2 = a0.z & b0.z, x3 = a0.w & b0.w;
    uint32_t x4 = a1.x & b1.x, x5 = a1.y & b1.y;
    uint32_t x6 = a1.z & b1.z, x7 = a1.w & b1.w;
    uint32_t s0 = xor3(x0, x1, x2), c0 = maj3(x0, x1, x2);
    uint32_t s1 = xor3(x3, x4, x5), c1 = maj3(x3, x4, x5);
    uint32_t S  = xor3(s0, s1, x6), c2 = maj3(s0, s1, x6);
    uint32_t C  = xor3(c0, c1, c2), CC = maj3(c0, c1, c2);
    acc += __popc(S) + __popc(x7)
         + 2 * __popc(C) + 4 * __popc(CC);
}

__device__ __forceinline__ uint4 lds128(uint32_t addr)
{
    uint4 v;
    asm volatile("ld.shared.v4.u32 {%0,%1,%2,%3}, [%4];"
                 : "=r"(v.x), "=r"(v.y), "=r"(v.z), "=r"(v.w) : "r"(addr));
    return v;
}

__global__ void __launch_bounds__(256, 1) popc_gemm3(const float* __restrict__ bias,
                                                     float* __restrict__ out)
{
    extern __shared__ char smraw[];
    uint32_t sb = smem_u32(smraw);

    int tid = threadIdx.x;
    int tx  = tid & 15;
    int ty  = tid >> 4;
    int row0 = blockIdx.y * 128;
    int col0 = blockIdx.x * 128;

    // stage loader (same swizzle as v2): row r, 16B chunk ch at (ch^(r&7))*16
    auto load_stage = [&](int kt, int s) {
        uint32_t dst0 = sb + (uint32_t)s * (2 * STG);
#pragma unroll
        for (int q = 0; q < 8; ++q) {
            int task = tid + q * 256;          // 0..2047
            int mat  = task >> 10;             // 0 = A, 1 = B
            int rem  = task & 1023;
            int r    = rem >> 3;
            int ch   = rem & 7;
            uint32_t dst = dst0 + (uint32_t)mat * STG + (uint32_t)r * 128
                         + (uint32_t)((ch ^ (r & 7)) << 4);
            const uint32_t* src = mat
                ? &g_Wpack[(size_t)(col0 + r) * ROW_WORDS + kt * CW + ch * 4]
                : &g_Apack[(size_t)(row0 + r) * ROW_WORDS + kt * CW + ch * 4];
            cp16(dst, src);
        }
    };

    int acc[8][8];
#pragma unroll
    for (int i = 0; i < 8; ++i)
#pragma unroll
        for (int j = 0; j < 8; ++j) acc[i][j] = 0;

    load_stage(0, 0); CP_COMMIT();
    load_stage(1, 1); CP_COMMIT();

    uint32_t sA7 = (uint32_t)(ty & 7);
    uint32_t sB7 = (uint32_t)(tx & 7);

    for (int kt = 0; kt < NCH; ++kt) {
        if (kt < NCH - 2) { CP_WAIT1(); } else { CP_WAIT0(); }
        __syncthreads();

        uint32_t Ab = sb + (uint32_t)(kt & 1) * (2 * STG);
        uint32_t Bb = Ab + STG;

#pragma unroll
        for (int g = 0; g < 4; ++g) {           // group of 8 words = chunks 2g, 2g+1
            uint32_t chA0 = ((uint32_t)(2 * g)     ^ sA7) << 4;
            uint32_t chA1 = ((uint32_t)(2 * g + 1) ^ sA7) << 4;
            uint32_t chB0 = ((uint32_t)(2 * g)     ^ sB7) << 4;
            uint32_t chB1 = ((uint32_t)(2 * g + 1) ^ sB7) << 4;

            uint4 av0[8], av1[8];
#pragma unroll
            for (int i = 0; i < 8; ++i) {
                uint32_t rb = Ab + (uint32_t)(ty + 16 * i) * 128;
                av0[i] = lds128(rb + chA0);
                av1[i] = lds128(rb + chA1);
            }
#pragma unroll
            for (int jp = 0; jp < 2; ++jp) {     // two j-passes of 4 (reg pressure)
                uint4 bv0[4], bv1[4];
#pragma unroll
                for (int j4 = 0; j4 < 4; ++j4) {
                    uint32_t rb = Bb + (uint32_t)(tx + 16 * (jp * 4 + j4)) * 128;
                    bv0[j4] = lds128(rb + chB0);
                    bv1[j4] = lds128(rb + chB1);
                }
#pragma unroll
                for (int i = 0; i < 8; ++i)
#pragma unroll
                    for (int j4 = 0; j4 < 4; ++j4)
                        csa8(acc[i][jp * 4 + j4], av0[i], av1[i], bv0[j4], bv1[j4]);
            }
        }
        __syncthreads();
        if (kt + 2 < NCH) { load_stage(kt + 2, kt & 1); CP_COMMIT(); }
    }

    // epilogue: out = 0.5*S - 0.25*(sA+sB) + 2048 + bias   (exact in fp32)
#pragma unroll
    for (int i = 0; i < 8; ++i) {
        int row = row0 + ty + 16 * i;
        float sa = (float)__ldg(&g_sA[row]);
        float* orow = out + (size_t)row * N_DIM;
#pragma unroll
        for (int j = 0; j < 8; ++j) {
            int col = col0 + tx + 16 * j;
            float s = (float)acc[i][j];
            orow[col] = 0.5f * s - 0.25f * (sa + (float)__ldg(&g_sB[col]))
                      + 2048.0f + __ldg(&bias[col]);
        }
    }
}

// ---------------------------------------------------------------------------
extern "C" void kernel_launch(void* const* d_in, const int* in_sizes, int n_in,
                              void* d_out, int out_size)
{
    const float* x    = (const float*)d_in[0];
    const float* w    = (const float*)d_in[1];
    const float* bias = (const float*)d_in[2];
    float* out        = (float*)d_out;

    // jax.random.split(jax.random.key(42)), partitionable (foldlike)
    uint32_t kA0, kA1, kB0, kB1;
    tf2x32(0u, 42u, 0u, 0u, kA0, kA1);
    tf2x32(0u, 42u, 0u, 1u, kB0, kB1);

    cudaFuncSetAttribute(popc_gemm3,
                         cudaFuncAttributeMaxDynamicSharedMemorySize, SMEM_BYTES);

    zero_counts<<<16, 256>>>();
    gen_bits_A<<<B_DIM / 4, 256>>>(x, kA0, kA1);
    gen_bits_W<<<N_DIM / 4, 256>>>(w, kB0, kB1);
    popc_gemm3<<<dim3(N_DIM / 128, B_DIM / 128), 256, SMEM_BYTES>>>(bias, out);
}